// round 1
// baseline (speedup 1.0000x reference)
#include <cuda_runtime.h>

#define NN 100000
#define NE 1600000
#define CHUNK 512
#define NCH ((NN + CHUNK - 1) / CHUNK)   // 196

// ---- scratch (static device globals; no allocation allowed) ----
__device__ float g_hA[NN * 256];
__device__ float g_hB[NN * 256];
__device__ float g_hN[NN * 256];
__device__ int   g_deg[NN];
__device__ int   g_rowptr[NN + 1];
__device__ int   g_cursor[NN];
__device__ int   g_csr[NE];
__device__ int   g_csum[NCH];

// ======================= CSR build =======================

__global__ void k_zero_deg() {
    int i = blockIdx.x * blockDim.x + threadIdx.x;
    if (i < NN) g_deg[i] = 0;
}

__global__ void k_hist(const int* __restrict__ dst) {
    int e = blockIdx.x * blockDim.x + threadIdx.x;
    if (e < NE) atomicAdd(&g_deg[dst[e]], 1);
}

__global__ void k_chunksum() {
    int c = blockIdx.x * blockDim.x + threadIdx.x;
    if (c < NCH) {
        int base = c * CHUNK;
        int end = base + CHUNK; if (end > NN) end = NN;
        int s = 0;
        for (int i = base; i < end; i++) s += g_deg[i];
        g_csum[c] = s;
    }
}

__global__ void k_scanchunks() {
    if (threadIdx.x == 0) {
        int run = 0;
        for (int c = 0; c < NCH; c++) {
            int t = g_csum[c];
            g_csum[c] = run;
            run += t;
        }
        g_rowptr[NN] = run;   // == NE
    }
}

__global__ void k_fill() {
    int c = blockIdx.x * blockDim.x + threadIdx.x;
    if (c < NCH) {
        int base = c * CHUNK;
        int end = base + CHUNK; if (end > NN) end = NN;
        int run = g_csum[c];
        for (int i = base; i < end; i++) {
            g_rowptr[i] = run;
            g_cursor[i] = run;
            run += g_deg[i];
        }
    }
}

__global__ void k_scatter(const int* __restrict__ src, const int* __restrict__ dst) {
    int e = blockIdx.x * blockDim.x + threadIdx.x;
    if (e < NE) {
        int p = atomicAdd(&g_cursor[dst[e]], 1);
        g_csr[p] = src[e];
    }
}

// ======================= aggregation (mean of neighbor features) =======================
// One warp per node. DV = number of float4 chunks per lane (d/128): 1 for d=128, 2 for d=256.

template <int DV>
__global__ void k_agg(const float* __restrict__ h, float* __restrict__ out) {
    int gwarp = (blockIdx.x * blockDim.x + threadIdx.x) >> 5;
    int lane = threadIdx.x & 31;
    if (gwarp >= NN) return;

    int s0 = g_rowptr[gwarp];
    int s1 = g_rowptr[gwarp + 1];

    float4 acc[DV];
#pragma unroll
    for (int j = 0; j < DV; j++) acc[j] = make_float4(0.f, 0.f, 0.f, 0.f);

    const int stride4 = DV * 32;               // d / 4
    const float4* __restrict__ hv = (const float4*)h;

    for (int e = s0; e < s1; e++) {
        int s = g_csr[e];
        const float4* row = hv + (long)s * stride4;
#pragma unroll
        for (int j = 0; j < DV; j++) {
            float4 v = row[lane + 32 * j];
            acc[j].x += v.x; acc[j].y += v.y; acc[j].z += v.z; acc[j].w += v.w;
        }
    }

    int deg = s1 - s0;
    float inv = 1.0f / (float)(deg > 0 ? deg : 1);
    float4* ov = (float4*)out + (long)gwarp * stride4;
#pragma unroll
    for (int j = 0; j < DV; j++) {
        float4 r;
        r.x = acc[j].x * inv; r.y = acc[j].y * inv;
        r.z = acc[j].z * inv; r.w = acc[j].w * inv;
        ov[lane + 32 * j] = r;
    }
}

// ======================= fused concat-GEMM =======================
// C[M, Nout] = [A1 | A2] @ W^T + bias, optional ReLU.
// A1, A2: [M, d] row-major; W: [Nout, 2d] row-major (K-contiguous).
// BLOCK_M=128, BLOCK_N=64, BK=16, 256 threads, 8x4 per-thread micro-tile.

template <bool RELU>
__global__ void __launch_bounds__(256, 2)
k_gemm(const float* __restrict__ A1, const float* __restrict__ A2,
       const float* __restrict__ W, const float* __restrict__ bias,
       float* __restrict__ C, int M, int Nout, int d) {
    __shared__ float As[16][132];   // [k][m], padded (528B row => 16B aligned)
    __shared__ float Bs[16][68];    // [k][n], padded (272B row => 16B aligned)

    const int tid = threadIdx.x;
    const int tx = tid & 15;        // n group: 4 cols
    const int ty = tid >> 4;        // m group: 8 rows
    const int m0 = blockIdx.x * 128;
    const int n0 = blockIdx.y * 64;
    const int K = 2 * d;

    float acc[8][4];
#pragma unroll
    for (int r = 0; r < 8; r++)
#pragma unroll
        for (int c = 0; c < 4; c++) acc[r][c] = 0.f;

    for (int k0 = 0; k0 < K; k0 += 16) {
        const float* A = (k0 < d) ? A1 : A2;
        const int ka = (k0 < d) ? k0 : (k0 - d);

        // load A tile: 128 rows x 16 k = 512 float4; 2 per thread; transpose into smem
#pragma unroll
        for (int i = 0; i < 2; i++) {
            int f4 = tid + i * 256;
            int row = f4 >> 2;
            int kq = (f4 & 3) * 4;
            int gr = m0 + row;
            float4 v = make_float4(0.f, 0.f, 0.f, 0.f);
            if (gr < M) v = *(const float4*)(A + (long)gr * d + ka + kq);
            As[kq + 0][row] = v.x;
            As[kq + 1][row] = v.y;
            As[kq + 2][row] = v.z;
            As[kq + 3][row] = v.w;
        }
        // load W tile: 64 rows x 16 k = 256 float4; 1 per thread
        {
            int n = tid >> 2;
            int kq = (tid & 3) * 4;
            float4 v = *(const float4*)(W + (long)(n0 + n) * K + k0 + kq);
            Bs[kq + 0][n] = v.x;
            Bs[kq + 1][n] = v.y;
            Bs[kq + 2][n] = v.z;
            Bs[kq + 3][n] = v.w;
        }
        __syncthreads();

#pragma unroll
        for (int k = 0; k < 16; k++) {
            float4 a0 = *(const float4*)&As[k][ty * 8];
            float4 a1 = *(const float4*)&As[k][ty * 8 + 4];
            float4 bb = *(const float4*)&Bs[k][tx * 4];
            float a[8] = {a0.x, a0.y, a0.z, a0.w, a1.x, a1.y, a1.z, a1.w};
            float b[4] = {bb.x, bb.y, bb.z, bb.w};
#pragma unroll
            for (int r = 0; r < 8; r++)
#pragma unroll
                for (int c = 0; c < 4; c++) acc[r][c] = fmaf(a[r], b[c], acc[r][c]);
        }
        __syncthreads();
    }

#pragma unroll
    for (int r = 0; r < 8; r++) {
        int gr = m0 + ty * 8 + r;
        if (gr < M) {
#pragma unroll
            for (int c = 0; c < 4; c++) {
                int gn = n0 + tx * 4 + c;
                float v = acc[r][c] + bias[gn];
                if (RELU) v = v > 0.f ? v : 0.f;
                C[(long)gr * Nout + gn] = v;
            }
        }
    }
}

// ======================= launch =======================

extern "C" void kernel_launch(void* const* d_in, const int* in_sizes, int n_in,
                              void* d_out, int out_size) {
    const float* x   = (const float*)d_in[0];
    const int*   src = (const int*)d_in[1];
    const int*   dst = (const int*)d_in[2];
    const float* W1  = (const float*)d_in[3];
    const float* b1  = (const float*)d_in[4];
    const float* W2  = (const float*)d_in[5];
    const float* b2  = (const float*)d_in[6];
    const float* W3  = (const float*)d_in[7];
    const float* b3  = (const float*)d_in[8];
    float* out = (float*)d_out;

    float* hA = nullptr; float* hB = nullptr; float* hN = nullptr;
    cudaGetSymbolAddress((void**)&hA, g_hA);
    cudaGetSymbolAddress((void**)&hB, g_hB);
    cudaGetSymbolAddress((void**)&hN, g_hN);

    // --- CSR build (per launch; edges are inputs) ---
    k_zero_deg<<<(NN + 255) / 256, 256>>>();
    k_hist<<<(NE + 255) / 256, 256>>>(dst);
    k_chunksum<<<1, 256>>>();
    k_scanchunks<<<1, 32>>>();
    k_fill<<<1, 256>>>();
    k_scatter<<<(NE + 255) / 256, 256>>>(src, dst);

    const int AGG_BLOCKS = (NN + 7) / 8;   // 8 warps / block, 1 warp / node
    const int GM = (NN + 127) / 128;       // 782

    // layer 1: d=128 -> 256, ReLU
    k_agg<1><<<AGG_BLOCKS, 256>>>(x, hN);
    k_gemm<true><<<dim3(GM, 4), 256>>>(x, hN, W1, b1, hA, NN, 256, 128);

    // layer 2: d=256 -> 256, ReLU
    k_agg<2><<<AGG_BLOCKS, 256>>>(hA, hN);
    k_gemm<true><<<dim3(GM, 4), 256>>>(hA, hN, W2, b2, hB, NN, 256, 256);

    // layer 3: d=256 -> 64, no activation
    k_agg<2><<<AGG_BLOCKS, 256>>>(hB, hN);
    k_gemm<false><<<dim3(GM, 1), 256>>>(hB, hN, W3, b3, out, NN, 64, 256);
}

// round 4
// speedup vs baseline: 1.0362x; 1.0362x over previous
#include <cuda_runtime.h>

#define NN 100000
#define NNP 100096            // padded to multiple of 128 (782 * 128)
#define NE 1600000
#define CHUNK 512
#define NCH ((NN + CHUNK - 1) / CHUNK)   // 196

// ---- scratch (static device globals; zero-initialized; no allocation allowed) ----
__device__ float g_xh[NNP * 128];       // x hi/lo (padded)
__device__ float g_xl[NNP * 128];
__device__ float g_hNh[NNP * 256];      // aggregated neighbor feats hi/lo (reused per layer)
__device__ float g_hNl[NNP * 256];
__device__ float g_hAf[NNP * 256];      // layer-1 output: full, hi, lo
__device__ float g_hAh[NNP * 256];
__device__ float g_hAl[NNP * 256];
__device__ float g_hBf[NNP * 256];      // layer-2 output: full, hi, lo
__device__ float g_hBh[NNP * 256];
__device__ float g_hBl[NNP * 256];
__device__ float g_W1h[256 * 256];
__device__ float g_W1l[256 * 256];
__device__ float g_W2h[256 * 512];
__device__ float g_W2l[256 * 512];
__device__ float g_W3h[64 * 512];
__device__ float g_W3l[64 * 512];
__device__ int   g_deg[NN];
__device__ int   g_rowptr[NN + 1];
__device__ int   g_cursor[NN];
__device__ int   g_csr[NE];
__device__ int   g_csum[NCH];

// ======================= helpers =======================

__device__ __forceinline__ float tf32r(float x) {
    float y;
    asm("cvt.rna.tf32.f32 %0, %1;" : "=f"(y) : "f"(x));
    return y;
}

__device__ __forceinline__ unsigned smem_u32(const void* p) {
    unsigned a;
    asm("{ .reg .u64 t; cvta.to.shared.u64 t, %1; cvt.u32.u64 %0, t; }" : "=r"(a) : "l"(p));
    return a;
}

__device__ __forceinline__ void cp16(unsigned dst, const void* src) {
    asm volatile("cp.async.cg.shared.global [%0], [%1], 16;" :: "r"(dst), "l"(src));
}
#define CP_COMMIT() asm volatile("cp.async.commit_group;" ::: "memory")
#define CP_WAIT1()  asm volatile("cp.async.wait_group 1;" ::: "memory")

__device__ __forceinline__ void mma8(float* c, const unsigned* a, const unsigned* b) {
    asm volatile(
        "mma.sync.aligned.m16n8k8.row.col.f32.tf32.tf32.f32 "
        "{%0,%1,%2,%3}, {%4,%5,%6,%7}, {%8,%9}, {%0,%1,%2,%3};"
        : "+f"(c[0]), "+f"(c[1]), "+f"(c[2]), "+f"(c[3])
        : "r"(a[0]), "r"(a[1]), "r"(a[2]), "r"(a[3]), "r"(b[0]), "r"(b[1]));
}

// ======================= CSR build =======================

__global__ void k_zero_deg() {
    int i = blockIdx.x * blockDim.x + threadIdx.x;
    if (i < NN) g_deg[i] = 0;
}

__global__ void k_hist(const int* __restrict__ dst) {
    int e = blockIdx.x * blockDim.x + threadIdx.x;
    if (e < NE) atomicAdd(&g_deg[dst[e]], 1);
}

__global__ void k_chunksum() {
    int c = blockIdx.x * blockDim.x + threadIdx.x;
    if (c < NCH) {
        int base = c * CHUNK;
        int end = base + CHUNK; if (end > NN) end = NN;
        int s = 0;
        for (int i = base; i < end; i++) s += g_deg[i];
        g_csum[c] = s;
    }
}

__global__ void k_scanchunks() {
    if (threadIdx.x == 0) {
        int run = 0;
        for (int c = 0; c < NCH; c++) {
            int t = g_csum[c];
            g_csum[c] = run;
            run += t;
        }
        g_rowptr[NN] = run;
    }
}

__global__ void k_fill() {
    int c = blockIdx.x * blockDim.x + threadIdx.x;
    if (c < NCH) {
        int base = c * CHUNK;
        int end = base + CHUNK; if (end > NN) end = NN;
        int run = g_csum[c];
        for (int i = base; i < end; i++) {
            g_rowptr[i] = run;
            g_cursor[i] = run;
            run += g_deg[i];
        }
    }
}

__global__ void k_scatter(const int* __restrict__ src, const int* __restrict__ dst) {
    int e = blockIdx.x * blockDim.x + threadIdx.x;
    if (e < NE) {
        int p = atomicAdd(&g_cursor[dst[e]], 1);
        g_csr[p] = src[e];
    }
}

// ======================= input prep (hi/lo split) =======================

__device__ __forceinline__ void split4(float4 v, float4& hi, float4& lo) {
    hi.x = tf32r(v.x); lo.x = tf32r(v.x - hi.x);
    hi.y = tf32r(v.y); lo.y = tf32r(v.y - hi.y);
    hi.z = tf32r(v.z); lo.z = tf32r(v.z - hi.z);
    hi.w = tf32r(v.w); lo.w = tf32r(v.w - hi.w);
}

__global__ void k_copy_x(const float* __restrict__ x) {
    int i = blockIdx.x * blockDim.x + threadIdx.x;
    if (i < NN * 32) {
        float4 hi, lo;
        split4(((const float4*)x)[i], hi, lo);
        ((float4*)g_xh)[i] = hi;
        ((float4*)g_xl)[i] = lo;
    }
}

__global__ void k_split_w(const float* __restrict__ W, float* __restrict__ oh,
                          float* __restrict__ ol, int n4) {
    int i = blockIdx.x * blockDim.x + threadIdx.x;
    if (i < n4) {
        float4 hi, lo;
        split4(((const float4*)W)[i], hi, lo);
        ((float4*)oh)[i] = hi;
        ((float4*)ol)[i] = lo;
    }
}

// ======================= aggregation (mean of neighbor features) =======================
// One warp per node; writes hi/lo split of the mean.

template <int DV>
__global__ void k_agg(const float* __restrict__ h, float* __restrict__ oh,
                      float* __restrict__ ol) {
    int gwarp = (blockIdx.x * blockDim.x + threadIdx.x) >> 5;
    int lane = threadIdx.x & 31;
    if (gwarp >= NN) return;

    int s0 = g_rowptr[gwarp];
    int s1 = g_rowptr[gwarp + 1];

    float4 acc[DV];
#pragma unroll
    for (int j = 0; j < DV; j++) acc[j] = make_float4(0.f, 0.f, 0.f, 0.f);

    const int stride4 = DV * 32;
    const float4* __restrict__ hv = (const float4*)h;

    for (int e = s0; e < s1; e++) {
        int s = g_csr[e];
        const float4* row = hv + (long)s * stride4;
#pragma unroll
        for (int j = 0; j < DV; j++) {
            float4 v = row[lane + 32 * j];
            acc[j].x += v.x; acc[j].y += v.y; acc[j].z += v.z; acc[j].w += v.w;
        }
    }

    int deg = s1 - s0;
    float inv = 1.0f / (float)(deg > 0 ? deg : 1);
    float4* ovh = (float4*)oh + (long)gwarp * stride4;
    float4* ovl = (float4*)ol + (long)gwarp * stride4;
#pragma unroll
    for (int j = 0; j < DV; j++) {
        float4 v;
        v.x = acc[j].x * inv; v.y = acc[j].y * inv;
        v.z = acc[j].z * inv; v.w = acc[j].w * inv;
        float4 hi, lo;
        split4(v, hi, lo);
        ovh[lane + 32 * j] = hi;
        ovl[lane + 32 * j] = lo;
    }
}

// ======================= 3xTF32 mma.sync concat-GEMM =======================
// C[M, N_OUT] = [A1 | A2] @ W^T + bias, computed as
//   A_hi.B_hi + A_hi.B_lo + A_lo.B_hi  (fp32 accumulate; error ~2^-22)
// Implemented as a 3x-long K sweep over the same double-buffered pipeline.
// Block: 128(M) x BN(N), 256 threads (8 warps, 4Mx2N). Smem stride 36.

template <int N_OUT, int BN, int D, bool RELU, bool SPLIT_OUT>
__global__ void __launch_bounds__(256, 2)
k_mma(const float* __restrict__ A1h, const float* __restrict__ A2h,
      const float* __restrict__ A1l, const float* __restrict__ A2l,
      const float* __restrict__ Wh,  const float* __restrict__ Wl,
      const float* __restrict__ bias,
      float* __restrict__ C, float* __restrict__ Ch, float* __restrict__ Cl) {
    constexpr int K = 2 * D;
    constexpr int NC = K / 32;                 // chunks per phase
    constexpr int NC3 = 3 * NC;                // total chunks (hi.hi, hi.lo, lo.hi)
    constexpr int NT = BN / 16;                // n-tiles (of 8) per warp
    constexpr int WN = BN / 2;                 // warp n extent
    constexpr int A_FLOATS = 128 * 36;
    constexpr int B_FLOATS = BN * 36;
    constexpr int STAGE_B = (A_FLOATS + B_FLOATS) * 4;
    constexpr int BLD = BN * 8 / 256;

    extern __shared__ char smem_raw[];
    const unsigned sbase = smem_u32(smem_raw);

    const int tid = threadIdx.x;
    const int wid = tid >> 5;
    const int lane = tid & 31;
    const int wm = wid & 3;
    const int wn = wid >> 2;
    const int n0 = blockIdx.x * BN;
    const int m0 = blockIdx.y * 128;

    const int lr = lane >> 2;
    const int lc = lane & 3;

    float acc[2][NT][4];
#pragma unroll
    for (int mt = 0; mt < 2; mt++)
#pragma unroll
        for (int nt = 0; nt < NT; nt++)
#pragma unroll
            for (int q = 0; q < 4; q++) acc[mt][nt][q] = 0.f;

    auto load_chunk = [&](int j, int s) {
        unsigned base = sbase + s * STAGE_B;
        int p = j / NC;                        // phase 0: hi.hi, 1: hi.lo, 2: lo.hi
        int kc = j - p * NC;
        int k0 = kc * 32;
        const float* A = (p < 2) ? ((k0 < D) ? A1h : A2h)
                                 : ((k0 < D) ? A1l : A2l);
        const float* B = (p == 1) ? Wl : Wh;
        int ka = (k0 < D) ? k0 : (k0 - D);
#pragma unroll
        for (int q = 0; q < 4; q++) {
            int idx = tid + 256 * q;
            int row = idx >> 3, kq = (idx & 7) * 4;
            cp16(base + (unsigned)(row * 36 + kq) * 4,
                 A + (long)(m0 + row) * D + ka + kq);
        }
#pragma unroll
        for (int q = 0; q < BLD; q++) {
            int idx = tid + 256 * q;
            int n = idx >> 3, kq = (idx & 7) * 4;
            cp16(base + (unsigned)(A_FLOATS + n * 36 + kq) * 4,
                 B + (long)(n0 + n) * K + k0 + kq);
        }
        CP_COMMIT();
    };

    load_chunk(0, 0);
    load_chunk(1, 1);

#pragma unroll 1
    for (int i = 0; i < NC3; i++) {
        int s = i & 1;
        CP_WAIT1();
        __syncthreads();

        const float* As = (const float*)(smem_raw + s * STAGE_B);
        const float* Bs = As + A_FLOATS;

#pragma unroll
        for (int ks = 0; ks < 4; ks++) {
            int kb = ks * 8 + lc;
            unsigned a[2][4];
#pragma unroll
            for (int mt = 0; mt < 2; mt++) {
                int mb = wm * 32 + mt * 16 + lr;
                a[mt][0] = __float_as_uint(As[mb * 36 + kb]);
                a[mt][1] = __float_as_uint(As[(mb + 8) * 36 + kb]);
                a[mt][2] = __float_as_uint(As[mb * 36 + kb + 4]);
                a[mt][3] = __float_as_uint(As[(mb + 8) * 36 + kb + 4]);
            }
            unsigned b[NT][2];
#pragma unroll
            for (int nt = 0; nt < NT; nt++) {
                int nb = wn * WN + nt * 8 + lr;
                b[nt][0] = __float_as_uint(Bs[nb * 36 + kb]);
                b[nt][1] = __float_as_uint(Bs[nb * 36 + kb + 4]);
            }
#pragma unroll
            for (int mt = 0; mt < 2; mt++)
#pragma unroll
                for (int nt = 0; nt < NT; nt++)
                    mma8(acc[mt][nt], a[mt], b[nt]);
        }

        __syncthreads();
        if (i + 2 < NC3) load_chunk(i + 2, s);
    }

    // epilogue: bias + relu; write full (and hi/lo split for next layer's GEMM)
#pragma unroll
    for (int mt = 0; mt < 2; mt++) {
#pragma unroll
        for (int nt = 0; nt < NT; nt++) {
            int n = n0 + wn * WN + nt * 8 + lc * 2;
            float b0 = bias[n], b1 = bias[n + 1];
            int r0 = m0 + wm * 32 + mt * 16 + lr;
#pragma unroll
            for (int h = 0; h < 2; h++) {
                int r = r0 + h * 8;
                if (r < NN) {
                    float v0 = acc[mt][nt][2 * h + 0] + b0;
                    float v1 = acc[mt][nt][2 * h + 1] + b1;
                    if (RELU) { v0 = v0 > 0.f ? v0 : 0.f; v1 = v1 > 0.f ? v1 : 0.f; }
                    long off = (long)r * N_OUT + n;
                    *(float2*)(C + off) = make_float2(v0, v1);
                    if (SPLIT_OUT) {
                        float h0 = tf32r(v0), h1 = tf32r(v1);
                        *(float2*)(Ch + off) = make_float2(h0, h1);
                        *(float2*)(Cl + off) = make_float2(tf32r(v0 - h0), tf32r(v1 - h1));
                    }
                }
            }
        }
    }
}

// ======================= launch =======================

extern "C" void kernel_launch(void* const* d_in, const int* in_sizes, int n_in,
                              void* d_out, int out_size) {
    const float* x   = (const float*)d_in[0];
    const int*   src = (const int*)d_in[1];
    const int*   dst = (const int*)d_in[2];
    const float* W1  = (const float*)d_in[3];
    const float* b1  = (const float*)d_in[4];
    const float* W2  = (const float*)d_in[5];
    const float* b2  = (const float*)d_in[6];
    const float* W3  = (const float*)d_in[7];
    const float* b3  = (const float*)d_in[8];
    float* out = (float*)d_out;

    float *xh, *xl, *hNh, *hNl, *hAf, *hAh, *hAl, *hBf, *hBh, *hBl;
    float *W1h, *W1l, *W2h, *W2l, *W3h, *W3l;
    cudaGetSymbolAddress((void**)&xh, g_xh);
    cudaGetSymbolAddress((void**)&xl, g_xl);
    cudaGetSymbolAddress((void**)&hNh, g_hNh);
    cudaGetSymbolAddress((void**)&hNl, g_hNl);
    cudaGetSymbolAddress((void**)&hAf, g_hAf);
    cudaGetSymbolAddress((void**)&hAh, g_hAh);
    cudaGetSymbolAddress((void**)&hAl, g_hAl);
    cudaGetSymbolAddress((void**)&hBf, g_hBf);
    cudaGetSymbolAddress((void**)&hBh, g_hBh);
    cudaGetSymbolAddress((void**)&hBl, g_hBl);
    cudaGetSymbolAddress((void**)&W1h, g_W1h);
    cudaGetSymbolAddress((void**)&W1l, g_W1l);
    cudaGetSymbolAddress((void**)&W2h, g_W2h);
    cudaGetSymbolAddress((void**)&W2l, g_W2l);
    cudaGetSymbolAddress((void**)&W3h, g_W3h);
    cudaGetSymbolAddress((void**)&W3l, g_W3l);

    constexpr int SM_BN128 = 2 * (128 * 36 + 128 * 36) * 4;   // 73728
    constexpr int SM_BN64  = 2 * (128 * 36 + 64 * 36) * 4;    // 55296
    cudaFuncSetAttribute(k_mma<256, 128, 128, true,  true>,
                         cudaFuncAttributeMaxDynamicSharedMemorySize, SM_BN128);
    cudaFuncSetAttribute(k_mma<256, 128, 256, true,  true>,
                         cudaFuncAttributeMaxDynamicSharedMemorySize, SM_BN128);
    cudaFuncSetAttribute(k_mma<64,  64,  256, false, false>,
                         cudaFuncAttributeMaxDynamicSharedMemorySize, SM_BN64);

    // --- input prep + CSR build ---
    k_copy_x<<<(NN * 32 + 255) / 256, 256>>>(x);
    k_split_w<<<(256 * 256 / 4 + 255) / 256, 256>>>(W1, W1h, W1l, 256 * 256 / 4);
    k_split_w<<<(256 * 512 / 4 + 255) / 256, 256>>>(W2, W2h, W2l, 256 * 512 / 4);
    k_split_w<<<(64 * 512 / 4 + 255) / 256, 256>>>(W3, W3h, W3l, 64 * 512 / 4);
    k_zero_deg<<<(NN + 255) / 256, 256>>>();
    k_hist<<<(NE + 255) / 256, 256>>>(dst);
    k_chunksum<<<1, 256>>>();
    k_scanchunks<<<1, 32>>>();
    k_fill<<<1, 256>>>();
    k_scatter<<<(NE + 255) / 256, 256>>>(src, dst);

    const int AGG_BLOCKS = (NN + 7) / 8;
    const int GM = NNP / 128;   // 782

    // layer 1: d=128 -> 256, ReLU   (agg reads original x, full precision)
    k_agg<1><<<AGG_BLOCKS, 256>>>(x, hNh, hNl);
    k_mma<256, 128, 128, true, true><<<dim3(2, GM), 256, SM_BN128>>>(
        xh, hNh, xl, hNl, W1h, W1l, b1, hAf, hAh, hAl);

    // layer 2: d=256 -> 256, ReLU
    k_agg<2><<<AGG_BLOCKS, 256>>>(hAf, hNh, hNl);
    k_mma<256, 128, 256, true, true><<<dim3(2, GM), 256, SM_BN128>>>(
        hAh, hNh, hAl, hNl, W2h, W2l, b2, hBf, hBh, hBl);

    // layer 3: d=256 -> 64, no activation
    k_agg<2><<<AGG_BLOCKS, 256>>>(hBf, hNh, hNl);
    k_mma<64, 64, 256, false, false><<<dim3(1, GM), 256, SM_BN64>>>(
        hBh, hNh, hBl, hNl, W3h, W3l, b3, out, out, out);
}

// round 5
// speedup vs baseline: 1.6427x; 1.5853x over previous
#include <cuda_runtime.h>
#include <cuda_fp16.h>

#define NN 100000
#define NNP 100096            // padded to multiple of 128 (782 * 128)
#define NE 1600000
#define CHUNK 512
#define NCH ((NN + CHUNK - 1) / CHUNK)   // 196

// ---- scratch (static device globals; zero-initialized; no allocation allowed) ----
__device__ __half g_xh[NNP * 128];      // x hi/lo (fp16 split, padded)
__device__ __half g_xl[NNP * 128];
__device__ __half g_hNh[NNP * 256];     // aggregated neighbor feats hi/lo
__device__ __half g_hNl[NNP * 256];
__device__ float  g_hAf[NNP * 256];     // layer-1 output full (agg input for L2)
__device__ __half g_hAh[NNP * 256];
__device__ __half g_hAl[NNP * 256];
__device__ __half g_hBh[NNP * 256];     // layer-2 output (hi/lo only)
__device__ __half g_hBl[NNP * 256];
__device__ float  g_z[NNP * 128];       // layer-3 GEMM out: [z_self | z_neigh]
__device__ __half g_W1h[256 * 256];
__device__ __half g_W1l[256 * 256];
__device__ __half g_W2h[256 * 512];
__device__ __half g_W2l[256 * 512];
__device__ __half g_W3h[128 * 256];    // stacked [W3_self; W3_neigh]
__device__ __half g_W3l[128 * 256];
__device__ int   g_deg[NN];
__device__ int   g_rowptr[NN + 1];
__device__ int   g_cursor[NN];
__device__ int   g_csr[NE];
__device__ int   g_csum[NCH];

// ======================= helpers =======================

__device__ __forceinline__ void splith(float v, __half& h, __half& l) {
    h = __float2half_rn(v);
    l = __float2half_rn(v - __half2float(h));
}

__device__ __forceinline__ unsigned smem_u32(const void* p) {
    unsigned a;
    asm("{ .reg .u64 t; cvta.to.shared.u64 t, %1; cvt.u32.u64 %0, t; }" : "=r"(a) : "l"(p));
    return a;
}

__device__ __forceinline__ void cp16(unsigned dst, const void* src) {
    asm volatile("cp.async.cg.shared.global [%0], [%1], 16;" :: "r"(dst), "l"(src));
}
#define CP_COMMIT() asm volatile("cp.async.commit_group;" ::: "memory")
#define CP_WAIT1()  asm volatile("cp.async.wait_group 1;" ::: "memory")

__device__ __forceinline__ void mma16(float* c, const unsigned* a, const unsigned* b) {
    asm volatile(
        "mma.sync.aligned.m16n8k16.row.col.f32.f16.f16.f32 "
        "{%0,%1,%2,%3}, {%4,%5,%6,%7}, {%8,%9}, {%0,%1,%2,%3};"
        : "+f"(c[0]), "+f"(c[1]), "+f"(c[2]), "+f"(c[3])
        : "r"(a[0]), "r"(a[1]), "r"(a[2]), "r"(a[3]), "r"(b[0]), "r"(b[1]));
}

// ======================= CSR build =======================

__global__ void k_zero_deg() {
    int i = blockIdx.x * blockDim.x + threadIdx.x;
    if (i < NN) g_deg[i] = 0;
}

__global__ void k_hist(const int* __restrict__ dst) {
    int e = blockIdx.x * blockDim.x + threadIdx.x;
    if (e < NE) atomicAdd(&g_deg[dst[e]], 1);
}

__global__ void k_chunksum() {
    int c = blockIdx.x * blockDim.x + threadIdx.x;
    if (c < NCH) {
        int base = c * CHUNK;
        int end = base + CHUNK; if (end > NN) end = NN;
        int s = 0;
        for (int i = base; i < end; i++) s += g_deg[i];
        g_csum[c] = s;
    }
}

__global__ void k_scanchunks() {
    if (threadIdx.x == 0) {
        int run = 0;
        for (int c = 0; c < NCH; c++) {
            int t = g_csum[c];
            g_csum[c] = run;
            run += t;
        }
        g_rowptr[NN] = run;
    }
}

__global__ void k_fill() {
    int c = blockIdx.x * blockDim.x + threadIdx.x;
    if (c < NCH) {
        int base = c * CHUNK;
        int end = base + CHUNK; if (end > NN) end = NN;
        int run = g_csum[c];
        for (int i = base; i < end; i++) {
            g_rowptr[i] = run;
            g_cursor[i] = run;
            run += g_deg[i];
        }
    }
}

__global__ void k_scatter(const int* __restrict__ src, const int* __restrict__ dst) {
    int e = blockIdx.x * blockDim.x + threadIdx.x;
    if (e < NE) {
        int p = atomicAdd(&g_cursor[dst[e]], 1);
        g_csr[p] = src[e];
    }
}

// ======================= input prep (fp16 hi/lo split) =======================

__global__ void k_copy_x(const float* __restrict__ x) {
    int i = blockIdx.x * blockDim.x + threadIdx.x;   // float4 index
    if (i < NN * 32) {
        float4 v = ((const float4*)x)[i];
        __half h0, h1, h2, h3, l0, l1, l2, l3;
        splith(v.x, h0, l0); splith(v.y, h1, l1);
        splith(v.z, h2, l2); splith(v.w, h3, l3);
        ((__half2*)g_xh)[2 * i]     = __halves2half2(h0, h1);
        ((__half2*)g_xh)[2 * i + 1] = __halves2half2(h2, h3);
        ((__half2*)g_xl)[2 * i]     = __halves2half2(l0, l1);
        ((__half2*)g_xl)[2 * i + 1] = __halves2half2(l2, l3);
    }
}

__global__ void k_split_w(const float* __restrict__ W, __half* __restrict__ oh,
                          __half* __restrict__ ol, int n) {
    int i = blockIdx.x * blockDim.x + threadIdx.x;
    if (i < n) {
        __half h, l;
        splith(W[i], h, l);
        oh[i] = h; ol[i] = l;
    }
}

// stacked W3: rows 0-63 = W3[:, 0:256] (self), rows 64-127 = W3[:, 256:512] (neigh)
__global__ void k_prep_w3(const float* __restrict__ W3) {
    int i = blockIdx.x * blockDim.x + threadIdx.x;   // 0 .. 128*256-1
    if (i < 128 * 256) {
        int r = i >> 8, c = i & 255;
        float v = (r < 64) ? W3[r * 512 + c] : W3[(r - 64) * 512 + 256 + c];
        __half h, l;
        splith(v, h, l);
        g_W3h[i] = h; g_W3l[i] = l;
    }
}

// ======================= aggregation (mean of neighbor features) =======================
// One warp per node; fp32 gather + accumulate; writes fp16 hi/lo split of the mean.

template <int DV>
__global__ void k_agg(const float* __restrict__ h, __half* __restrict__ oh,
                      __half* __restrict__ ol) {
    int gwarp = (blockIdx.x * blockDim.x + threadIdx.x) >> 5;
    int lane = threadIdx.x & 31;
    if (gwarp >= NN) return;

    int s0 = g_rowptr[gwarp];
    int s1 = g_rowptr[gwarp + 1];

    float4 acc[DV];
#pragma unroll
    for (int j = 0; j < DV; j++) acc[j] = make_float4(0.f, 0.f, 0.f, 0.f);

    const int stride4 = DV * 32;
    const float4* __restrict__ hv = (const float4*)h;

    for (int e = s0; e < s1; e++) {
        int s = g_csr[e];
        const float4* row = hv + (long)s * stride4;
#pragma unroll
        for (int j = 0; j < DV; j++) {
            float4 v = row[lane + 32 * j];
            acc[j].x += v.x; acc[j].y += v.y; acc[j].z += v.z; acc[j].w += v.w;
        }
    }

    int deg = s1 - s0;
    float inv = 1.0f / (float)(deg > 0 ? deg : 1);
    __half2* ovh = (__half2*)oh + (long)gwarp * (stride4 * 2);
    __half2* ovl = (__half2*)ol + (long)gwarp * (stride4 * 2);
#pragma unroll
    for (int j = 0; j < DV; j++) {
        float4 v;
        v.x = acc[j].x * inv; v.y = acc[j].y * inv;
        v.z = acc[j].z * inv; v.w = acc[j].w * inv;
        __half h0, h1, h2, h3, l0, l1, l2, l3;
        splith(v.x, h0, l0); splith(v.y, h1, l1);
        splith(v.z, h2, l2); splith(v.w, h3, l3);
        int f = lane + 32 * j;
        ovh[2 * f]     = __halves2half2(h0, h1);
        ovh[2 * f + 1] = __halves2half2(h2, h3);
        ovl[2 * f]     = __halves2half2(l0, l1);
        ovl[2 * f + 1] = __halves2half2(l2, l3);
    }
}

// ======================= layer-3 final: out = z_self + mean(z_neigh) + b =======================
// z: [NNP, 128], cols 0-63 self part, 64-127 neighbor part. One warp per node, 2 cols/lane.

__global__ void k_agg_out(const float* __restrict__ z, const float* __restrict__ b3,
                          float* __restrict__ out) {
    int gwarp = (blockIdx.x * blockDim.x + threadIdx.x) >> 5;
    int lane = threadIdx.x & 31;
    if (gwarp >= NN) return;

    int s0 = g_rowptr[gwarp];
    int s1 = g_rowptr[gwarp + 1];

    float2 acc = make_float2(0.f, 0.f);
    const float2* zn = (const float2*)(z + 64);   // neighbor half, float2 view
    for (int e = s0; e < s1; e++) {
        int s = g_csr[e];
        float2 v = zn[(long)s * 64 + lane];
        acc.x += v.x; acc.y += v.y;
    }
    int deg = s1 - s0;
    float inv = 1.0f / (float)(deg > 0 ? deg : 1);

    float2 self = ((const float2*)z)[(long)gwarp * 64 + lane];
    float2 bb = ((const float2*)b3)[lane];
    float2 r;
    r.x = self.x + acc.x * inv + bb.x;
    r.y = self.y + acc.y * inv + bb.y;
    ((float2*)out)[(long)gwarp * 32 + lane] = r;
}

// ======================= fp16 3-product mma.sync concat-GEMM =======================
// C[M, N_OUT] = [A1 | A2] @ W^T (+ bias, optional ReLU), computed as
//   A_hi.B_hi + A_hi.B_lo + A_lo.B_hi  (fp16 operands, fp32 accumulate; err ~2^-21)
// Block: 128(M) x BN=128(N), 256 threads (8 warps, 4Mx2N), warp tile 32x64.
// K chunks of 64 halves (128B rows), double-buffered cp.async. Smem stride 72 halves
// => conflict-free fragment LDS. OMODE: 0 = fp32 full only, 1 = full + fp16 split,
// 2 = fp16 split only.

template <int N_OUT, int K, bool CONCAT, bool RELU, int OMODE>
__global__ void __launch_bounds__(256, 2)
k_mma(const __half* __restrict__ A1h, const __half* __restrict__ A2h,
      const __half* __restrict__ A1l, const __half* __restrict__ A2l,
      const __half* __restrict__ Wh,  const __half* __restrict__ Wl,
      const float* __restrict__ bias,
      float* __restrict__ Cf, __half* __restrict__ Ch, __half* __restrict__ Cl) {
    constexpr int BN = 128;
    constexpr int D = CONCAT ? K / 2 : K;      // source row width
    constexpr int NCP = K / 64;                // chunks per phase
    constexpr int NC3 = 3 * NCP;
    constexpr int NT = 8;                      // n-tiles of 8 per warp (64 wide)
    constexpr int SH = 72;                     // smem stride in halves
    constexpr int A_BYTES = 128 * SH * 2;      // 18432
    constexpr int STAGE_B = 2 * A_BYTES;       // A + B

    extern __shared__ char smem_raw[];
    const unsigned sbase = smem_u32(smem_raw);

    const int tid = threadIdx.x;
    const int wid = tid >> 5;
    const int lane = tid & 31;
    const int wm = wid & 3;
    const int wn = wid >> 2;
    const int n0 = blockIdx.x * BN;
    const int m0 = blockIdx.y * 128;

    const int lr = lane >> 2;
    const int lc = lane & 3;

    float acc[2][NT][4];
#pragma unroll
    for (int mt = 0; mt < 2; mt++)
#pragma unroll
        for (int nt = 0; nt < NT; nt++)
#pragma unroll
            for (int q = 0; q < 4; q++) acc[mt][nt][q] = 0.f;

    auto load_chunk = [&](int j, int s) {
        unsigned base = sbase + s * STAGE_B;
        int p = j / NCP;                       // 0: hi.hi, 1: hi.lo, 2: lo.hi
        int kc = j - p * NCP;
        int k0 = kc * 64;
        const __half* A;
        int ka;
        if (CONCAT && k0 >= D) {
            A = (p < 2) ? A2h : A2l; ka = k0 - D;
        } else {
            A = (p < 2) ? A1h : A1l; ka = k0;
        }
        const __half* B = (p == 1) ? Wl : Wh;
        // A tile: 128 rows x 8 cp16 = 1024; 4 per thread
#pragma unroll
        for (int q = 0; q < 4; q++) {
            int idx = tid + 256 * q;
            int row = idx >> 3, c8 = idx & 7;
            cp16(base + (unsigned)(row * (SH * 2) + c8 * 16),
                 A + (long)(m0 + row) * D + ka + c8 * 8);
        }
        // B tile: BN rows x 8 cp16; 4 per thread
#pragma unroll
        for (int q = 0; q < 4; q++) {
            int idx = tid + 256 * q;
            int n = idx >> 3, c8 = idx & 7;
            cp16(base + (unsigned)(A_BYTES + n * (SH * 2) + c8 * 16),
                 B + (long)(n0 + n) * K + k0 + c8 * 8);
        }
        CP_COMMIT();
    };

    load_chunk(0, 0);
    load_chunk(1, 1);

#pragma unroll 1
    for (int i = 0; i < NC3; i++) {
        int s = i & 1;
        CP_WAIT1();
        __syncthreads();

        const __half* As = (const __half*)(smem_raw + s * STAGE_B);
        const __half* Bs = (const __half*)(smem_raw + s * STAGE_B + A_BYTES);

#pragma unroll
        for (int ks = 0; ks < 4; ks++) {
            int kb = ks * 16 + 2 * lc;
            unsigned a[2][4];
#pragma unroll
            for (int mt = 0; mt < 2; mt++) {
                int mb = wm * 32 + mt * 16 + lr;
                a[mt][0] = *(const unsigned*)&As[mb * SH + kb];
                a[mt][1] = *(const unsigned*)&As[(mb + 8) * SH + kb];
                a[mt][2] = *(const unsigned*)&As[mb * SH + kb + 8];
                a[mt][3] = *(const unsigned*)&As[(mb + 8) * SH + kb + 8];
            }
            unsigned b[NT][2];
#pragma unroll
            for (int nt = 0; nt < NT; nt++) {
                int nb = wn * 64 + nt * 8 + lr;
                b[nt][0] = *(const unsigned*)&Bs[nb * SH + kb];
                b[nt][1] = *(const unsigned*)&Bs[nb * SH + kb + 8];
            }
#pragma unroll
            for (int mt = 0; mt < 2; mt++)
#pragma unroll
                for (int nt = 0; nt < NT; nt++)
                    mma16(acc[mt][nt], a[mt], b[nt]);
        }

        __syncthreads();
        if (i + 2 < NC3) load_chunk(i + 2, s);
    }

    // epilogue
#pragma unroll
    for (int mt = 0; mt < 2; mt++) {
#pragma unroll
        for (int nt = 0; nt < NT; nt++) {
            int n = n0 + wn * 64 + nt * 8 + lc * 2;
            float b0 = 0.f, b1 = 0.f;
            if (OMODE != 0) { b0 = bias[n]; b1 = bias[n + 1]; }
            int r0 = m0 + wm * 32 + mt * 16 + lr;
#pragma unroll
            for (int h = 0; h < 2; h++) {
                int r = r0 + h * 8;
                if (r < NN) {
                    float v0 = acc[mt][nt][2 * h + 0] + b0;
                    float v1 = acc[mt][nt][2 * h + 1] + b1;
                    if (RELU) { v0 = v0 > 0.f ? v0 : 0.f; v1 = v1 > 0.f ? v1 : 0.f; }
                    long off = (long)r * N_OUT + n;
                    if (OMODE == 0 || OMODE == 1)
                        *(float2*)(Cf + off) = make_float2(v0, v1);
                    if (OMODE == 1 || OMODE == 2) {
                        __half h0, h1, l0, l1;
                        splith(v0, h0, l0); splith(v1, h1, l1);
                        ((__half2*)Ch)[off >> 1] = __halves2half2(h0, h1);
                        ((__half2*)Cl)[off >> 1] = __halves2half2(l0, l1);
                    }
                }
            }
        }
    }
}

// ======================= launch =======================

extern "C" void kernel_launch(void* const* d_in, const int* in_sizes, int n_in,
                              void* d_out, int out_size) {
    const float* x   = (const float*)d_in[0];
    const int*   src = (const int*)d_in[1];
    const int*   dst = (const int*)d_in[2];
    const float* W1  = (const float*)d_in[3];
    const float* b1  = (const float*)d_in[4];
    const float* W2  = (const float*)d_in[5];
    const float* b2  = (const float*)d_in[6];
    const float* W3  = (const float*)d_in[7];
    const float* b3  = (const float*)d_in[8];
    float* out = (float*)d_out;

    __half *xh, *xl, *hNh, *hNl, *hAh, *hAl, *hBh, *hBl;
    __half *W1h, *W1l, *W2h, *W2l, *W3h, *W3l;
    float *hAf, *z;
    cudaGetSymbolAddress((void**)&xh, g_xh);
    cudaGetSymbolAddress((void**)&xl, g_xl);
    cudaGetSymbolAddress((void**)&hNh, g_hNh);
    cudaGetSymbolAddress((void**)&hNl, g_hNl);
    cudaGetSymbolAddress((void**)&hAf, g_hAf);
    cudaGetSymbolAddress((void**)&hAh, g_hAh);
    cudaGetSymbolAddress((void**)&hAl, g_hAl);
    cudaGetSymbolAddress((void**)&hBh, g_hBh);
    cudaGetSymbolAddress((void**)&hBl, g_hBl);
    cudaGetSymbolAddress((void**)&z, g_z);
    cudaGetSymbolAddress((void**)&W1h, g_W1h);
    cudaGetSymbolAddress((void**)&W1l, g_W1l);
    cudaGetSymbolAddress((void**)&W2h, g_W2h);
    cudaGetSymbolAddress((void**)&W2l, g_W2l);
    cudaGetSymbolAddress((void**)&W3h, g_W3h);
    cudaGetSymbolAddress((void**)&W3l, g_W3l);

    constexpr int SMB = 2 * 2 * 128 * 72 * 2;   // 73728
    cudaFuncSetAttribute(k_mma<256, 256, true,  true,  1>,
                         cudaFuncAttributeMaxDynamicSharedMemorySize, SMB);
    cudaFuncSetAttribute(k_mma<256, 512, true,  true,  2>,
                         cudaFuncAttributeMaxDynamicSharedMemorySize, SMB);
    cudaFuncSetAttribute(k_mma<128, 256, false, false, 0>,
                         cudaFuncAttributeMaxDynamicSharedMemorySize, SMB);

    // --- input prep + CSR build ---
    k_copy_x<<<(NN * 32 + 255) / 256, 256>>>(x);
    k_split_w<<<(256 * 256 + 255) / 256, 256>>>(W1, W1h, W1l, 256 * 256);
    k_split_w<<<(256 * 512 + 255) / 256, 256>>>(W2, W2h, W2l, 256 * 512);
    k_prep_w3<<<(128 * 256 + 255) / 256, 256>>>(W3);
    k_zero_deg<<<(NN + 255) / 256, 256>>>();
    k_hist<<<(NE + 255) / 256, 256>>>(dst);
    k_chunksum<<<1, 256>>>();
    k_scanchunks<<<1, 32>>>();
    k_fill<<<1, 256>>>();
    k_scatter<<<(NE + 255) / 256, 256>>>(src, dst);

    const int AGG_BLOCKS = (NN + 7) / 8;
    const int GM = NNP / 128;   // 782

    // layer 1: [x | agg(x)] (K=256) -> 256, ReLU
    k_agg<1><<<AGG_BLOCKS, 256>>>(x, hNh, hNl);
    k_mma<256, 256, true, true, 1><<<dim3(2, GM), 256, SMB>>>(
        xh, hNh, xl, hNl, W1h, W1l, b1, hAf, hAh, hAl);

    // layer 2: [hA | agg(hA)] (K=512) -> 256, ReLU
    k_agg<2><<<AGG_BLOCKS, 256>>>(hAf, hNh, hNl);
    k_mma<256, 512, true, true, 2><<<dim3(2, GM), 256, SMB>>>(
        hAh, hNh, hAl, hNl, W2h, W2l, b2, nullptr, hBh, hBl);

    // layer 3 (reordered): z = hB @ [W_self; W_neigh]^T (K=256 -> 128), then
    // out = z_self + mean(z_neigh) + b3
    k_mma<128, 256, false, false, 0><<<dim3(1, GM), 256, SMB>>>(
        hBh, hBh, hBl, hBl, W3h, W3l, nullptr, z, nullptr, nullptr);
    k_agg_out<<<AGG_BLOCKS, 256>>>(z, b3, out);
}

// round 6
// speedup vs baseline: 1.7083x; 1.0399x over previous
#include <cuda_runtime.h>
#include <cuda_fp16.h>

#define NN 100000
#define NNP 100096            // padded to multiple of 128 (782 * 128)
#define NE 1600000
#define CHUNK 512
#define NCH ((NN + CHUNK - 1) / CHUNK)   // 196

// ---- scratch (static device globals; zero-initialized; no allocation allowed) ----
__device__ __half g_xh[NNP * 128];      // x hi/lo (fp16 split, padded)
__device__ __half g_xl[NNP * 128];
__device__ __half g_hNh[NNP * 256];     // aggregated neighbor feats hi/lo
__device__ __half g_hNl[NNP * 256];
__device__ float  g_hAf[NNP * 256];     // layer-1 output full (agg input for L2)
__device__ __half g_hAh[NNP * 256];
__device__ __half g_hAl[NNP * 256];
__device__ __half g_hBh[NNP * 256];     // layer-2 output (hi/lo only)
__device__ __half g_hBl[NNP * 256];
__device__ float  g_z[NNP * 128];       // layer-3 GEMM out: [z_self | z_neigh]
__device__ __half g_W1h[256 * 256];
__device__ __half g_W1l[256 * 256];
__device__ __half g_W2h[256 * 512];
__device__ __half g_W2l[256 * 512];
__device__ __half g_W3h[128 * 256];    // stacked [W3_self; W3_neigh]
__device__ __half g_W3l[128 * 256];
__device__ int   g_deg[NN];
__device__ int   g_rowptr[NN + 1];
__device__ int   g_cursor[NN];
__device__ int   g_csr[NE];
__device__ int   g_csum[NCH];

// ======================= helpers =======================

__device__ __forceinline__ void splith(float v, __half& h, __half& l) {
    h = __float2half_rn(v);
    l = __float2half_rn(v - __half2float(h));
}

__device__ __forceinline__ unsigned smem_u32(const void* p) {
    unsigned a;
    asm("{ .reg .u64 t; cvta.to.shared.u64 t, %1; cvt.u32.u64 %0, t; }" : "=r"(a) : "l"(p));
    return a;
}

__device__ __forceinline__ void cp16(unsigned dst, const void* src) {
    asm volatile("cp.async.cg.shared.global [%0], [%1], 16;" :: "r"(dst), "l"(src));
}
#define CP_COMMIT() asm volatile("cp.async.commit_group;" ::: "memory")
#define CP_WAIT1()  asm volatile("cp.async.wait_group 1;" ::: "memory")

__device__ __forceinline__ void mma16(float* c, const unsigned* a, const unsigned* b) {
    asm volatile(
        "mma.sync.aligned.m16n8k16.row.col.f32.f16.f16.f32 "
        "{%0,%1,%2,%3}, {%4,%5,%6,%7}, {%8,%9}, {%0,%1,%2,%3};"
        : "+f"(c[0]), "+f"(c[1]), "+f"(c[2]), "+f"(c[3])
        : "r"(a[0]), "r"(a[1]), "r"(a[2]), "r"(a[3]), "r"(b[0]), "r"(b[1]));
}

__device__ __forceinline__ void ldm_x4(unsigned& r0, unsigned& r1, unsigned& r2,
                                       unsigned& r3, unsigned addr) {
    asm volatile("ldmatrix.sync.aligned.m8n8.x4.shared.b16 {%0,%1,%2,%3}, [%4];"
                 : "=r"(r0), "=r"(r1), "=r"(r2), "=r"(r3) : "r"(addr));
}

// ======================= CSR build =======================

__global__ void k_zero_deg() {
    int i = blockIdx.x * blockDim.x + threadIdx.x;
    if (i < NN) g_deg[i] = 0;
}

__global__ void k_hist(const int* __restrict__ dst) {
    int e = blockIdx.x * blockDim.x + threadIdx.x;
    if (e < NE) atomicAdd(&g_deg[dst[e]], 1);
}

__global__ void k_chunksum() {
    int c = blockIdx.x * blockDim.x + threadIdx.x;
    if (c < NCH) {
        int base = c * CHUNK;
        int end = base + CHUNK; if (end > NN) end = NN;
        int s = 0;
        for (int i = base; i < end; i++) s += g_deg[i];
        g_csum[c] = s;
    }
}

__global__ void k_scanchunks() {
    if (threadIdx.x == 0) {
        int run = 0;
        for (int c = 0; c < NCH; c++) {
            int t = g_csum[c];
            g_csum[c] = run;
            run += t;
        }
        g_rowptr[NN] = run;
    }
}

__global__ void k_fill() {
    int c = blockIdx.x * blockDim.x + threadIdx.x;
    if (c < NCH) {
        int base = c * CHUNK;
        int end = base + CHUNK; if (end > NN) end = NN;
        int run = g_csum[c];
        for (int i = base; i < end; i++) {
            g_rowptr[i] = run;
            g_cursor[i] = run;
            run += g_deg[i];
        }
    }
}

__global__ void k_scatter(const int* __restrict__ src, const int* __restrict__ dst) {
    int e = blockIdx.x * blockDim.x + threadIdx.x;
    if (e < NE) {
        int p = atomicAdd(&g_cursor[dst[e]], 1);
        g_csr[p] = src[e];
    }
}

// ======================= input prep (fp16 hi/lo split) =======================

__global__ void k_copy_x(const float* __restrict__ x) {
    int i = blockIdx.x * blockDim.x + threadIdx.x;   // float4 index
    if (i < NN * 32) {
        float4 v = ((const float4*)x)[i];
        __half h0, h1, h2, h3, l0, l1, l2, l3;
        splith(v.x, h0, l0); splith(v.y, h1, l1);
        splith(v.z, h2, l2); splith(v.w, h3, l3);
        ((__half2*)g_xh)[2 * i]     = __halves2half2(h0, h1);
        ((__half2*)g_xh)[2 * i + 1] = __halves2half2(h2, h3);
        ((__half2*)g_xl)[2 * i]     = __halves2half2(l0, l1);
        ((__half2*)g_xl)[2 * i + 1] = __halves2half2(l2, l3);
    }
}

__global__ void k_split_w(const float* __restrict__ W, __half* __restrict__ oh,
                          __half* __restrict__ ol, int n) {
    int i = blockIdx.x * blockDim.x + threadIdx.x;
    if (i < n) {
        __half h, l;
        splith(W[i], h, l);
        oh[i] = h; ol[i] = l;
    }
}

// stacked W3: rows 0-63 = W3[:, 0:256] (self), rows 64-127 = W3[:, 256:512] (neigh)
__global__ void k_prep_w3(const float* __restrict__ W3) {
    int i = blockIdx.x * blockDim.x + threadIdx.x;   // 0 .. 128*256-1
    if (i < 128 * 256) {
        int r = i >> 8, c = i & 255;
        float v = (r < 64) ? W3[r * 512 + c] : W3[(r - 64) * 512 + 256 + c];
        __half h, l;
        splith(v, h, l);
        g_W3h[i] = h; g_W3l[i] = l;
    }
}

// ======================= aggregation (mean of neighbor features) =======================
// One warp per node; fp32 gather (2 edges in flight); fp16 hi/lo split output.

template <int DV>
__global__ void k_agg(const float* __restrict__ h, __half* __restrict__ oh,
                      __half* __restrict__ ol) {
    int gwarp = (blockIdx.x * blockDim.x + threadIdx.x) >> 5;
    int lane = threadIdx.x & 31;
    if (gwarp >= NN) return;

    int s0 = g_rowptr[gwarp];
    int s1 = g_rowptr[gwarp + 1];

    float4 acc[DV];
#pragma unroll
    for (int j = 0; j < DV; j++) acc[j] = make_float4(0.f, 0.f, 0.f, 0.f);

    const int stride4 = DV * 32;
    const float4* __restrict__ hv = (const float4*)h;

    int e = s0;
    for (; e + 1 < s1; e += 2) {
        const float4* ra = hv + (long)g_csr[e] * stride4;
        const float4* rb = hv + (long)g_csr[e + 1] * stride4;
        float4 va[DV], vb[DV];
#pragma unroll
        for (int j = 0; j < DV; j++) va[j] = ra[lane + 32 * j];
#pragma unroll
        for (int j = 0; j < DV; j++) vb[j] = rb[lane + 32 * j];
#pragma unroll
        for (int j = 0; j < DV; j++) {
            acc[j].x += va[j].x + vb[j].x;
            acc[j].y += va[j].y + vb[j].y;
            acc[j].z += va[j].z + vb[j].z;
            acc[j].w += va[j].w + vb[j].w;
        }
    }
    if (e < s1) {
        const float4* ra = hv + (long)g_csr[e] * stride4;
#pragma unroll
        for (int j = 0; j < DV; j++) {
            float4 v = ra[lane + 32 * j];
            acc[j].x += v.x; acc[j].y += v.y; acc[j].z += v.z; acc[j].w += v.w;
        }
    }

    int deg = s1 - s0;
    float inv = 1.0f / (float)(deg > 0 ? deg : 1);
    __half2* ovh = (__half2*)oh + (long)gwarp * (stride4 * 2);
    __half2* ovl = (__half2*)ol + (long)gwarp * (stride4 * 2);
#pragma unroll
    for (int j = 0; j < DV; j++) {
        float4 v;
        v.x = acc[j].x * inv; v.y = acc[j].y * inv;
        v.z = acc[j].z * inv; v.w = acc[j].w * inv;
        __half h0, h1, h2, h3, l0, l1, l2, l3;
        splith(v.x, h0, l0); splith(v.y, h1, l1);
        splith(v.z, h2, l2); splith(v.w, h3, l3);
        int f = lane + 32 * j;
        ovh[2 * f]     = __halves2half2(h0, h1);
        ovh[2 * f + 1] = __halves2half2(h2, h3);
        ovl[2 * f]     = __halves2half2(l0, l1);
        ovl[2 * f + 1] = __halves2half2(l2, l3);
    }
}

// ======================= layer-3 final: out = z_self + mean(z_neigh) + b =======================
// z: [NNP, 128], cols 0-63 self, 64-127 neighbor. One warp per node, 2 cols/lane.

__global__ void k_agg_out(const float* __restrict__ z, const float* __restrict__ b3,
                          float* __restrict__ out) {
    int gwarp = (blockIdx.x * blockDim.x + threadIdx.x) >> 5;
    int lane = threadIdx.x & 31;
    if (gwarp >= NN) return;

    int s0 = g_rowptr[gwarp];
    int s1 = g_rowptr[gwarp + 1];

    float2 acc = make_float2(0.f, 0.f);
    const float2* zn = (const float2*)(z + 64);   // neighbor half, float2 view
    int e = s0;
    for (; e + 1 < s1; e += 2) {
        float2 va = zn[(long)g_csr[e] * 64 + lane];
        float2 vb = zn[(long)g_csr[e + 1] * 64 + lane];
        acc.x += va.x + vb.x; acc.y += va.y + vb.y;
    }
    if (e < s1) {
        float2 v = zn[(long)g_csr[e] * 64 + lane];
        acc.x += v.x; acc.y += v.y;
    }
    int deg = s1 - s0;
    float inv = 1.0f / (float)(deg > 0 ? deg : 1);

    float2 self = ((const float2*)z)[(long)gwarp * 64 + lane];
    float2 bb = ((const float2*)b3)[lane];
    float2 r;
    r.x = self.x + acc.x * inv + bb.x;
    r.y = self.y + acc.y * inv + bb.y;
    ((float2*)out)[(long)gwarp * 32 + lane] = r;
}

// ======================= fp16 3-product mma.sync concat-GEMM =======================
// C[M, N_OUT] = [A1 | A2] @ W^T (+ bias, optional ReLU), computed as
//   A_hi.B_hi + A_hi.B_lo + A_lo.B_hi  (fp16 operands, fp32 accumulate)
// Block: 128(M) x 128(N), 256 threads (8 warps, 4Mx2N), warp tile 32x64.
// K chunks of 64 halves, double-buffered cp.async. Smem stride 72 halves —
// 144B row stride => ldmatrix 8-row accesses step 16B mod 128 => conflict-free.
// Fragments loaded via ldmatrix.m8n8.x4 (2 for A, 4 for B per ks step).

template <int N_OUT, int K, bool CONCAT, bool RELU, int OMODE>
__global__ void __launch_bounds__(256, 2)
k_mma(const __half* __restrict__ A1h, const __half* __restrict__ A2h,
      const __half* __restrict__ A1l, const __half* __restrict__ A2l,
      const __half* __restrict__ Wh,  const __half* __restrict__ Wl,
      const float* __restrict__ bias,
      float* __restrict__ Cf, __half* __restrict__ Ch, __half* __restrict__ Cl) {
    constexpr int BN = 128;
    constexpr int D = CONCAT ? K / 2 : K;      // source row width
    constexpr int NCP = K / 64;                // chunks per phase
    constexpr int NC3 = 3 * NCP;
    constexpr int NT = 8;                      // n-tiles of 8 per warp (64 wide)
    constexpr int SH = 72;                     // smem stride in halves
    constexpr int A_BYTES = 128 * SH * 2;      // 18432
    constexpr int STAGE_B = 2 * A_BYTES;       // A + B

    extern __shared__ char smem_raw[];
    const unsigned sbase = smem_u32(smem_raw);

    const int tid = threadIdx.x;
    const int wid = tid >> 5;
    const int lane = tid & 31;
    const int wm = wid & 3;
    const int wn = wid >> 2;
    const int n0 = blockIdx.x * BN;
    const int m0 = blockIdx.y * 128;

    const int lr = lane >> 2;
    const int lc = lane & 3;

    // ldmatrix per-lane byte offsets (relative to tile bases), ks = 0
    unsigned offA[2], offB[4];
#pragma unroll
    for (int mt = 0; mt < 2; mt++) {
        int row = wm * 32 + mt * 16 + (lane & 15);
        int col = (lane >> 4) * 8;
        offA[mt] = (unsigned)(row * SH + col) * 2;
    }
#pragma unroll
    for (int p = 0; p < 4; p++) {
        int row = wn * 64 + p * 16 + (lane & 7) + ((lane >> 4) & 1) * 8;
        int col = ((lane >> 3) & 1) * 8;
        offB[p] = (unsigned)(A_BYTES) + (unsigned)(row * SH + col) * 2;
    }

    float acc[2][NT][4];
#pragma unroll
    for (int mt = 0; mt < 2; mt++)
#pragma unroll
        for (int nt = 0; nt < NT; nt++)
#pragma unroll
            for (int q = 0; q < 4; q++) acc[mt][nt][q] = 0.f;

    auto load_chunk = [&](int j, int s) {
        unsigned base = sbase + s * STAGE_B;
        int p = j / NCP;                       // 0: hi.hi, 1: hi.lo, 2: lo.hi
        int kc = j - p * NCP;
        int k0 = kc * 64;
        const __half* A;
        int ka;
        if (CONCAT && k0 >= D) {
            A = (p < 2) ? A2h : A2l; ka = k0 - D;
        } else {
            A = (p < 2) ? A1h : A1l; ka = k0;
        }
        const __half* B = (p == 1) ? Wl : Wh;
#pragma unroll
        for (int q = 0; q < 4; q++) {
            int idx = tid + 256 * q;
            int row = idx >> 3, c8 = idx & 7;
            cp16(base + (unsigned)(row * (SH * 2) + c8 * 16),
                 A + (long)(m0 + row) * D + ka + c8 * 8);
        }
#pragma unroll
        for (int q = 0; q < 4; q++) {
            int idx = tid + 256 * q;
            int n = idx >> 3, c8 = idx & 7;
            cp16(base + (unsigned)(A_BYTES + n * (SH * 2) + c8 * 16),
                 B + (long)(n0 + n) * K + k0 + c8 * 8);
        }
        CP_COMMIT();
    };

    load_chunk(0, 0);
    load_chunk(1, 1);

#pragma unroll 1
    for (int i = 0; i < NC3; i++) {
        int s = i & 1;
        CP_WAIT1();
        __syncthreads();

        unsigned stage = sbase + s * STAGE_B;

#pragma unroll
        for (int ks = 0; ks < 4; ks++) {
            unsigned kso = ks * 32;            // 16 halves = 32 bytes
            unsigned a[2][4];
#pragma unroll
            for (int mt = 0; mt < 2; mt++)
                ldm_x4(a[mt][0], a[mt][1], a[mt][2], a[mt][3],
                       stage + offA[mt] + kso);
            unsigned b[NT][2];
#pragma unroll
            for (int p = 0; p < 4; p++)
                ldm_x4(b[2 * p][0], b[2 * p][1], b[2 * p + 1][0], b[2 * p + 1][1],
                       stage + offB[p] + kso);
#pragma unroll
            for (int mt = 0; mt < 2; mt++)
#pragma unroll
                for (int nt = 0; nt < NT; nt++)
                    mma16(acc[mt][nt], a[mt], b[nt]);
        }

        __syncthreads();
        if (i + 2 < NC3) load_chunk(i + 2, s);
    }

    // epilogue
#pragma unroll
    for (int mt = 0; mt < 2; mt++) {
#pragma unroll
        for (int nt = 0; nt < NT; nt++) {
            int n = n0 + wn * 64 + nt * 8 + lc * 2;
            float b0 = 0.f, b1 = 0.f;
            if (OMODE != 0) { b0 = bias[n]; b1 = bias[n + 1]; }
            int r0 = m0 + wm * 32 + mt * 16 + lr;
#pragma unroll
            for (int h = 0; h < 2; h++) {
                int r = r0 + h * 8;
                if (r < NN) {
                    float v0 = acc[mt][nt][2 * h + 0] + b0;
                    float v1 = acc[mt][nt][2 * h + 1] + b1;
                    if (RELU) { v0 = v0 > 0.f ? v0 : 0.f; v1 = v1 > 0.f ? v1 : 0.f; }
                    long off = (long)r * N_OUT + n;
                    if (OMODE == 0 || OMODE == 1)
                        *(float2*)(Cf + off) = make_float2(v0, v1);
                    if (OMODE == 1 || OMODE == 2) {
                        __half h0, h1, l0, l1;
                        splith(v0, h0, l0); splith(v1, h1, l1);
                        ((__half2*)Ch)[off >> 1] = __halves2half2(h0, h1);
                        ((__half2*)Cl)[off >> 1] = __halves2half2(l0, l1);
                    }
                }
            }
        }
    }
}

// ======================= launch =======================

extern "C" void kernel_launch(void* const* d_in, const int* in_sizes, int n_in,
                              void* d_out, int out_size) {
    const float* x   = (const float*)d_in[0];
    const int*   src = (const int*)d_in[1];
    const int*   dst = (const int*)d_in[2];
    const float* W1  = (const float*)d_in[3];
    const float* b1  = (const float*)d_in[4];
    const float* W2  = (const float*)d_in[5];
    const float* b2  = (const float*)d_in[6];
    const float* W3  = (const float*)d_in[7];
    const float* b3  = (const float*)d_in[8];
    float* out = (float*)d_out;

    __half *xh, *xl, *hNh, *hNl, *hAh, *hAl, *hBh, *hBl;
    __half *W1h, *W1l, *W2h, *W2l, *W3h, *W3l;
    float *hAf, *z;
    cudaGetSymbolAddress((void**)&xh, g_xh);
    cudaGetSymbolAddress((void**)&xl, g_xl);
    cudaGetSymbolAddress((void**)&hNh, g_hNh);
    cudaGetSymbolAddress((void**)&hNl, g_hNl);
    cudaGetSymbolAddress((void**)&hAf, g_hAf);
    cudaGetSymbolAddress((void**)&hAh, g_hAh);
    cudaGetSymbolAddress((void**)&hAl, g_hAl);
    cudaGetSymbolAddress((void**)&hBh, g_hBh);
    cudaGetSymbolAddress((void**)&hBl, g_hBl);
    cudaGetSymbolAddress((void**)&z, g_z);
    cudaGetSymbolAddress((void**)&W1h, g_W1h);
    cudaGetSymbolAddress((void**)&W1l, g_W1l);
    cudaGetSymbolAddress((void**)&W2h, g_W2h);
    cudaGetSymbolAddress((void**)&W2l, g_W2l);
    cudaGetSymbolAddress((void**)&W3h, g_W3h);
    cudaGetSymbolAddress((void**)&W3l, g_W3l);

    constexpr int SMB = 2 * 2 * 128 * 72 * 2;   // 73728
    cudaFuncSetAttribute(k_mma<256, 256, true,  true,  1>,
                         cudaFuncAttributeMaxDynamicSharedMemorySize, SMB);
    cudaFuncSetAttribute(k_mma<256, 512, true,  true,  2>,
                         cudaFuncAttributeMaxDynamicSharedMemorySize, SMB);
    cudaFuncSetAttribute(k_mma<128, 256, false, false, 0>,
                         cudaFuncAttributeMaxDynamicSharedMemorySize, SMB);

    // --- input prep + CSR build ---
    k_copy_x<<<(NN * 32 + 255) / 256, 256>>>(x);
    k_split_w<<<(256 * 256 + 255) / 256, 256>>>(W1, W1h, W1l, 256 * 256);
    k_split_w<<<(256 * 512 + 255) / 256, 256>>>(W2, W2h, W2l, 256 * 512);
    k_prep_w3<<<(128 * 256 + 255) / 256, 256>>>(W3);
    k_zero_deg<<<(NN + 255) / 256, 256>>>();
    k_hist<<<(NE + 255) / 256, 256>>>(dst);
    k_chunksum<<<1, 256>>>();
    k_scanchunks<<<1, 32>>>();
    k_fill<<<1, 256>>>();
    k_scatter<<<(NE + 255) / 256, 256>>>(src, dst);

    const int AGG_BLOCKS = (NN + 7) / 8;
    const int GM = NNP / 128;   // 782

    // layer 1: [x | agg(x)] (K=256) -> 256, ReLU
    k_agg<1><<<AGG_BLOCKS, 256>>>(x, hNh, hNl);
    k_mma<256, 256, true, true, 1><<<dim3(2, GM), 256, SMB>>>(
        xh, hNh, xl, hNl, W1h, W1l, b1, hAf, hAh, hAl);

    // layer 2: [hA | agg(hA)] (K=512) -> 256, ReLU
    k_agg<2><<<AGG_BLOCKS, 256>>>(hAf, hNh, hNl);
    k_mma<256, 512, true, true, 2><<<dim3(2, GM), 256, SMB>>>(
        hAh, hNh, hAl, hNl, W2h, W2l, b2, nullptr, hBh, hBl);

    // layer 3 (reordered): z = hB @ [W_self; W_neigh]^T (K=256 -> 128), then
    // out = z_self + mean(z_neigh) + b3
    k_mma<128, 256, false, false, 0><<<dim3(1, GM), 256, SMB>>>(
        hBh, hBh, hBl, hBl, W3h, W3l, nullptr, z, nullptr, nullptr);
    k_agg_out<<<AGG_BLOCKS, 256>>>(z, b3, out);
}